// round 3
// baseline (speedup 1.0000x reference)
#include <cuda_runtime.h>
#include <cstdint>

#define FULLM 0xffffffffu

namespace {
constexpr int T_STEPS = 128;
constexpr int NCH = 17;
constexpr int WARPS_PER_BLOCK = 4;
constexpr int WARP_FLOATS = T_STEPS * NCH;      // 2176
constexpr int WARP_F4 = WARP_FLOATS / 4;        // 544 = 17 * 32 exactly
}

// Inclusive scan over 32 per-lane block values, JAX associative_scan
// association (Brent-Kung odd/even recursion, combine(left, right)).
__device__ __forceinline__ float jax_scan32(float r, int lane) {
#pragma unroll
    for (int h = 1; h <= 16; h <<= 1) {
        float u = __shfl_up_sync(FULLM, r, h);
        if ((lane & (2 * h - 1)) == (2 * h - 1)) r = __fadd_rn(u, r);
    }
#pragma unroll
    for (int h = 8; h >= 1; h >>= 1) {
        float u = __shfl_up_sync(FULLM, r, h);
        if (lane >= 2 * h && (lane & (2 * h - 1)) == (h - 1)) r = __fadd_rn(u, r);
    }
    return r;
}

// Full-T (128) inclusive scan, JAX association. Lane L owns t = 4L..4L+3.
__device__ __forceinline__ void scan128(const float a[4], float s[4], int lane) {
    const float p = __fadd_rn(a[0], a[1]);
    const float q = __fadd_rn(a[2], a[3]);
    const float r = __fadd_rn(p, q);
    const float S = jax_scan32(r, lane);
    const float E = __shfl_up_sync(FULLM, S, 1);
    if (lane == 0) {
        s[0] = a[0];
        s[1] = p;
        s[2] = __fadd_rn(p, a[2]);
        s[3] = S;
    } else {
        s[0] = __fadd_rn(E, a[0]);
        s[1] = __fadd_rn(E, p);
        s[2] = __fadd_rn(s[1], a[2]);
        s[3] = S;
    }
}

__global__ __launch_bounds__(WARPS_PER_BLOCK * 32, 6)
void car_dyn_kernel(const float* __restrict__ state,
                    const float* __restrict__ pact,
                    const float* __restrict__ Hmap,
                    const float* __restrict__ Nrm,
                    float* __restrict__ out_states,
                    float* __restrict__ out_pa,
                    int K)
{
    __shared__ float buf[WARPS_PER_BLOCK * WARP_FLOATS];   // 34816 B / CTA

    const int wid  = threadIdx.x >> 5;
    const int lane = threadIdx.x & 31;
    const int k    = blockIdx.x * WARPS_PER_BLOCK + wid;
    if (k >= K) return;

    float*  sb  = buf + wid * WARP_FLOATS;
    float4* sb4 = reinterpret_cast<float4*>(sb);

    const float4* src4 = reinterpret_cast<const float4*>(state + (size_t)k * WARP_FLOATS);
    const float4* pin4 = reinterpret_cast<const float4*>(pact) + (size_t)k * (T_STEPS / 2);
    float4*       dst4 = reinterpret_cast<float4*>(out_states + (size_t)k * WARP_FLOATS);
    float4*       op4  = reinterpret_cast<float4*>(out_pa)    + (size_t)k * (T_STEPS / 2);

    // ---- load all 128 input records into smem (coalesced float4) ----
#pragma unroll
    for (int i = 0; i < 17; ++i) sb4[lane + 32 * i] = src4[lane + 32 * i];

    // ---- perturbed actions: lane L owns t = 4L..4L+3 ----
    const float4 pA = pin4[2 * lane];
    const float4 pB = pin4[2 * lane + 1];
    float pax[4] = {pA.x, pA.z, pB.x, pB.z};
    float pay[4] = {pA.y, pA.w, pB.y, pB.w};

    __syncwarp();

    const int rb = 4 * lane * NCH;      // this lane's first record in smem

    // ---- stage 1: controls = clip(ctrl0 + 4*cumsum(pa*DT)) ----
    float t0[4], t1[4];
#pragma unroll
    for (int m = 0; m < 4; ++m) {
        t0[m] = __fmul_rn(pax[m], 0.02f);
        t1[m] = __fmul_rn(pay[m], 0.02f);
    }
    float cs0[4], cs1[4];
    scan128(t0, cs0, lane);
    scan128(t1, cs1, lane);

    float steer[4], thr[4], cm0[4], cm1[4];
#pragma unroll
    for (int m = 0; m < 4; ++m) {
        float* rec = sb + rb + m * NCH;
        const float s15 = rec[15];
        const float s16 = rec[16];
        float c0 = fminf(fmaxf(__fadd_rn(s15, __fmul_rn(4.0f, cs0[m])), -1.f), 1.f);
        float c1 = fminf(fmaxf(__fadd_rn(s16, __fmul_rn(4.0f, cs1[m])), -1.f), 1.f);
        c1 = fminf(fmaxf(c1, 0.f), 0.5f);
        steer[m] = c0; thr[m] = c1;
        cm0[m] = __fsub_rn(c0, s15);
        cm1[m] = __fsub_rn(c1, s16);
        rec[15] = c0;                      // eager store: ch15/16 final
        rec[16] = c1;
        rec[7]  = 0.f;                     // vy
        rec[8]  = 0.f;                     // vz  (ch9 = ax passes through)
    }

    // ---- new_pa: write to global immediately, free regs ----
    {
        const float pcm0 = __shfl_up_sync(FULLM, cm0[3], 1);
        const float pcm1 = __shfl_up_sync(FULLM, cm1[3], 1);
        float np0[4], np1[4];
#pragma unroll
        for (int m = 0; m < 4; ++m) {
            const float pm0 = m ? cm0[m - 1] : pcm0;
            const float pm1 = m ? cm1[m - 1] : pcm1;
            np0[m] = __fdiv_rn(__fsub_rn(cm0[m], pm0), 0.08f);
            np1[m] = __fdiv_rn(__fsub_rn(cm1[m], pm1), 0.08f);
        }
        if (lane == 0) { np0[0] = pax[0]; np1[0] = pay[0]; }
        op4[2 * lane]     = make_float4(np0[0], np1[0], np0[1], np1[1]);
        op4[2 * lane + 1] = make_float4(np0[2], np1[2], np0[3], np1[3]);
    }

    // ---- dynamics elementwise ----
    float vx[4], dS[4], wzv[4];
#pragma unroll
    for (int m = 0; m < 4; ++m) {
        float* rec = sb + rb + m * NCH;
        const float Kc = __fdiv_rn(tanf(steer[m]), 0.5f);
        vx[m] = __fmul_rn(thr[m], 17.0f);
        dS[m] = __fmul_rn(vx[m], 0.02f);
        const float w1 = __fmul_rn(vx[m], Kc);
        const float a0 = fminf(fmaxf(__fmul_rn(vx[m], w1), -14.f), 14.f);
        wzv[m] = __fdiv_rn(a0, fminf(fmaxf(vx[m], 1.f), 25.f));
        rec[6]  = vx[m];                   // eager: ch6 vx
        rec[14] = wzv[m];                  // eager: ch14 wz
    }

    // ---- stage 2: yaw ----
    float cwz[4];
    scan128(wzv, cwz, lane);
    float cyv[4], syv[4];
#pragma unroll
    for (int m = 0; m < 4; ++m) {
        float* rec = sb + rb + m * NCH;
        const float yaw = __fadd_rn(rec[5], __fmul_rn(0.02f, cwz[m]));
        rec[5] = yaw;                      // eager: ch5 yaw
        cyv[m] = cosf(yaw);
        syv[m] = sinf(yaw);
    }

    // ---- stage 3: x, y + BEV index ----
    float tx[4], ty[4];
#pragma unroll
    for (int m = 0; m < 4; ++m) {
        tx[m] = __fmul_rn(dS[m], cyv[m]);
        ty[m] = __fmul_rn(dS[m], syv[m]);
    }
    float cx[4], cyy[4];
    scan128(tx, cx, lane);
    scan128(ty, cyy, lane);

    int g[4];
#pragma unroll
    for (int m = 0; m < 4; ++m) {
        float* rec = sb + rb + m * NCH;
        const float x = __fadd_rn(rec[0], cx[m]);
        const float y = __fadd_rn(rec[1], cyy[m]);
        rec[0] = x;                        // eager: ch0/ch1
        rec[1] = y;
        int iX = (int)(__fmul_rn(__fadd_rn(x, 32.f), 4.f));
        int iY = (int)(__fmul_rn(__fadd_rn(y, 32.f), 4.f));
        iX = min(max(iX, 0), 255);
        iY = min(max(iY, 0), 255);
        g[m] = iY * 256 + iX;
    }

    // ---- BEV gathers: issue all loads first (MLP), then use ----
    float zv[4], nxv[4], nyv[4], nzv[4];
#pragma unroll
    for (int m = 0; m < 4; ++m) {
        zv[m]  = __ldg(Hmap + g[m]);
        nxv[m] = __ldg(Nrm + 3 * g[m] + 0);
        nyv[m] = __ldg(Nrm + 3 * g[m] + 1);
        nzv[m] = __ldg(Nrm + 3 * g[m] + 2);
    }

    float rollv[4], pitchv[4];
#pragma unroll
    for (int m = 0; m < 4; ++m) {
        float* rec = sb + rb + m * NCH;
        const float lz = __fsub_rn(__fmul_rn(nxv[m], syv[m]), __fmul_rn(nyv[m], cyv[m]));
        const float lx = __fsub_rn(0.f, __fmul_rn(nzv[m], syv[m]));
        const float ly = __fmul_rn(nzv[m], cyv[m]);
        rollv[m] = asinf(lz);
        const float fz = __fsub_rn(__fmul_rn(lx, nyv[m]), __fmul_rn(ly, nxv[m]));
        pitchv[m] = -asinf(fz);
        rec[2]  = zv[m];                   // eager: ch2/3/4
        rec[3]  = rollv[m];
        rec[4]  = pitchv[m];
        rec[11] = nzv[m];                  // stash nz in ch11 (overwritten by az)
    }

    // ---- diff pass: wx, wy, ay, az ----
    {
        const float proll  = __shfl_up_sync(FULLM, rollv[3], 1);
        const float ppitch = __shfl_up_sync(FULLM, pitchv[3], 1);
#pragma unroll
        for (int m = 0; m < 4; ++m) {
            float* rec = sb + rb + m * NCH;
            const float pr = m ? rollv[m - 1]  : proll;
            const float pp = m ? pitchv[m - 1] : ppitch;
            float wx = __fdiv_rn(__fsub_rn(rollv[m],  pr), 0.02f);
            float wy = __fdiv_rn(__fsub_rn(pitchv[m], pp), 0.02f);
            if (lane == 0 && m == 0) {     // t=0: input ch12/13 (still intact)
                wx = rec[12];
                wy = rec[13];
            }
            const float vxm = rec[6];
            const float wzm = rec[14];
            const float nzm = rec[11];
            const float ay = __fadd_rn(__fmul_rn(vxm, wzm),
                                       __fmul_rn(9.8f, sinf(rollv[m])));
            const float az = __fadd_rn(__fmul_rn(__fsub_rn(0.f, vxm), wy),
                                       __fmul_rn(9.8f, nzm));
            rec[10] = ay;
            rec[11] = az;
            rec[12] = wx;
            rec[13] = wy;
        }
    }

    __syncwarp();

    // ---- single coalesced copy: smem -> global (all 32 lanes) ----
#pragma unroll
    for (int i = 0; i < 17; ++i) dst4[lane + 32 * i] = sb4[lane + 32 * i];
}

extern "C" void kernel_launch(void* const* d_in, const int* in_sizes, int n_in,
                              void* d_out, int out_size)
{
    const float* state = (const float*)d_in[0];
    const float* pact  = (const float*)d_in[1];
    const float* Hmap  = (const float*)d_in[2];
    const float* Nrm   = (const float*)d_in[3];

    const int K = (in_sizes[1] / 2) / T_STEPS;
    float* out_states = (float*)d_out;
    float* out_pa     = (float*)d_out + (size_t)in_sizes[0];

    const int blocks = (K + WARPS_PER_BLOCK - 1) / WARPS_PER_BLOCK;
    car_dyn_kernel<<<blocks, WARPS_PER_BLOCK * 32>>>(state, pact, Hmap, Nrm,
                                                     out_states, out_pa, K);
}

// round 4
// speedup vs baseline: 1.1403x; 1.1403x over previous
#include <cuda_runtime.h>
#include <cstdint>

#define FULLM 0xffffffffu

namespace {
constexpr int T_STEPS = 128;
constexpr int NCH = 17;
constexpr int IMG_FLOATS = T_STEPS * NCH;   // 2176
constexpr int IMG_F4 = IMG_FLOATS / 4;      // 544
}

// Within-warp upsweep of the 128-element JAX Brent-Kung tree (levels h=1..16).
__device__ __forceinline__ float scan_upsweep(float r, int lane) {
#pragma unroll
    for (int h = 1; h <= 16; h <<= 1) {
        float u = __shfl_up_sync(FULLM, r, h);
        if ((lane & (2 * h - 1)) == (2 * h - 1)) r = __fadd_rn(u, r);
    }
    return r;
}

// Within-warp downsweep with cross-warp prefix injection. T = 4 warp totals
// (smem). Bracketing matches the flat 128-element JAX associative_scan tree.
__device__ __forceinline__ float scan_downsweep(float r, int lane, int w,
                                                const float* __restrict__ T) {
    const float s1 = __fadd_rn(T[0], T[1]);
    const float S0 = T[0];
    const float S1 = s1;
    const float S2 = __fadd_rn(s1, T[2]);
    const float S3 = __fadd_rn(s1, __fadd_rn(T[2], T[3]));
    const float E  = (w == 1) ? S0 : (w == 2) ? S1 : S2;   // used only if w>0
    const float Sw = (w == 0) ? S0 : (w == 1) ? S1 : (w == 2) ? S2 : S3;
    if (lane == 31) r = Sw;   // positions 31,63,95,127: top-tree values
#pragma unroll
    for (int h = 16; h >= 1; h >>= 1) {
        float u = __shfl_up_sync(FULLM, r, h);
        if (lane == h - 1) u = E;                      // value at t-h = 32w-1
        const bool act = ((lane & (2 * h - 1)) == (h - 1)) &&
                         (w > 0 || lane >= 2 * h);
        if (act) r = __fadd_rn(u, r);
    }
    return r;
}

__global__ __launch_bounds__(128, 8)
void car_dyn_kernel(const float* __restrict__ state,
                    const float* __restrict__ pact,
                    const float* __restrict__ Hmap,
                    const float* __restrict__ Nrm,
                    float* __restrict__ out_states,
                    float* __restrict__ out_pa)
{
    __shared__ __align__(16) float img[IMG_FLOATS];   // 8704 B working image
    __shared__ float tot[5][4];                        // per-scan warp totals
    __shared__ float bnd[4][2];                        // warp-boundary values

    const int tid  = threadIdx.x;
    const int lane = tid & 31;
    const int w    = tid >> 5;
    const int k    = blockIdx.x;

    float4* img4 = reinterpret_cast<float4*>(img);
    const float4* src4 = reinterpret_cast<const float4*>(state) + (size_t)k * IMG_F4;
#pragma unroll
    for (int i = 0; i < 4; ++i) img4[tid + 128 * i] = src4[tid + 128 * i];
    if (tid < 32) img4[512 + tid] = src4[512 + tid];

    const float2 pa = reinterpret_cast<const float2*>(pact)[(size_t)k * T_STEPS + tid];

    __syncthreads();   // (1) image ready

    float* rec = img + tid * NCH;   // base 17*tid -> conflict-free scalar access

    // ---- scans 1&2: cumsum(pa * DT) ----
    float r0 = scan_upsweep(__fmul_rn(pa.x, 0.02f), lane);
    float r1 = scan_upsweep(__fmul_rn(pa.y, 0.02f), lane);
    if (lane == 31) { tot[0][w] = r0; tot[1][w] = r1; }
    __syncthreads();   // (2)
    r0 = scan_downsweep(r0, lane, w, tot[0]);
    r1 = scan_downsweep(r1, lane, w, tot[1]);

    // ---- controls ----
    const float s15 = rec[15], s16 = rec[16];
    float c0 = fminf(fmaxf(__fadd_rn(s15, __fmul_rn(4.0f, r0)), -1.f), 1.f);
    float c1 = fminf(fmaxf(__fadd_rn(s16, __fmul_rn(4.0f, r1)), -1.f), 1.f);
    c1 = fminf(fmaxf(c1, 0.f), 0.5f);
    const float cm0 = __fsub_rn(c0, s15);
    const float cm1 = __fsub_rn(c1, s16);
    rec[15] = c0; rec[16] = c1;
    rec[7] = 0.f; rec[8] = 0.f;    // vy, vz (ch9 = ax passes through untouched)

    // ---- dynamics elementwise ----
    const float Kc = __fdiv_rn(tanf(c0), 0.5f);
    const float vx = __fmul_rn(c1, 17.0f);
    const float dS = __fmul_rn(vx, 0.02f);
    const float w1 = __fmul_rn(vx, Kc);
    const float a0 = fminf(fmaxf(__fmul_rn(vx, w1), -14.f), 14.f);
    const float wz = __fdiv_rn(a0, fminf(fmaxf(vx, 1.f), 25.f));
    rec[6] = vx; rec[14] = wz;

    // ---- scan 3 upsweep (wz) + cm boundary exchange, one sync ----
    float r2 = scan_upsweep(wz, lane);
    if (lane == 31) { tot[2][w] = r2; bnd[w][0] = cm0; bnd[w][1] = cm1; }
    __syncthreads();   // (3)

    // ---- new_pa (uses cm boundary), written straight to global ----
    {
        float pm0 = __shfl_up_sync(FULLM, cm0, 1);
        float pm1 = __shfl_up_sync(FULLM, cm1, 1);
        if (lane == 0 && w > 0) { pm0 = bnd[w - 1][0]; pm1 = bnd[w - 1][1]; }
        float np0 = __fdiv_rn(__fsub_rn(cm0, pm0), 0.08f);
        float np1 = __fdiv_rn(__fsub_rn(cm1, pm1), 0.08f);
        if (tid == 0) { np0 = pa.x; np1 = pa.y; }
        reinterpret_cast<float2*>(out_pa)[(size_t)k * T_STEPS + tid] =
            make_float2(np0, np1);
    }

    r2 = scan_downsweep(r2, lane, w, tot[2]);
    const float yaw = __fadd_rn(rec[5], __fmul_rn(0.02f, r2));
    rec[5] = yaw;
    const float cy = cosf(yaw);
    const float sy = sinf(yaw);

    // ---- scans 4&5: x, y ----
    float r3 = scan_upsweep(__fmul_rn(dS, cy), lane);
    float r4 = scan_upsweep(__fmul_rn(dS, sy), lane);
    if (lane == 31) { tot[3][w] = r3; tot[4][w] = r4; }
    __syncthreads();   // (4)
    r3 = scan_downsweep(r3, lane, w, tot[3]);
    r4 = scan_downsweep(r4, lane, w, tot[4]);
    const float x = __fadd_rn(rec[0], r3);
    const float y = __fadd_rn(rec[1], r4);
    rec[0] = x; rec[1] = y;

    // ---- BEV gather ----
    int iX = (int)(__fmul_rn(__fadd_rn(x, 32.f), 4.f));
    int iY = (int)(__fmul_rn(__fadd_rn(y, 32.f), 4.f));
    iX = min(max(iX, 0), 255);
    iY = min(max(iY, 0), 255);
    const int g = iY * 256 + iX;
    const float z  = __ldg(Hmap + g);
    const float nx = __ldg(Nrm + 3 * g + 0);
    const float ny = __ldg(Nrm + 3 * g + 1);
    const float nz = __ldg(Nrm + 3 * g + 2);

    const float lz = __fsub_rn(__fmul_rn(nx, sy), __fmul_rn(ny, cy));
    const float lx = __fsub_rn(0.f, __fmul_rn(nz, sy));
    const float ly = __fmul_rn(nz, cy);
    const float roll = asinf(lz);
    const float fz = __fsub_rn(__fmul_rn(lx, ny), __fmul_rn(ly, nx));
    const float pitch = -asinf(fz);
    rec[2] = z; rec[3] = roll; rec[4] = pitch;

    // ---- roll/pitch boundary exchange ----
    if (lane == 31) { bnd[w][0] = roll; bnd[w][1] = pitch; }
    __syncthreads();   // (5)
    float pr = __shfl_up_sync(FULLM, roll, 1);
    float pp = __shfl_up_sync(FULLM, pitch, 1);
    if (lane == 0 && w > 0) { pr = bnd[w - 1][0]; pp = bnd[w - 1][1]; }
    float wxv = __fdiv_rn(__fsub_rn(roll, pr), 0.02f);
    float wyv = __fdiv_rn(__fsub_rn(pitch, pp), 0.02f);
    if (tid == 0) { wxv = rec[12]; wyv = rec[13]; }   // input ch12/13 still intact
    const float ay = __fadd_rn(__fmul_rn(vx, wz), __fmul_rn(9.8f, sinf(roll)));
    const float az = __fadd_rn(__fmul_rn(__fsub_rn(0.f, vx), wyv),
                               __fmul_rn(9.8f, nz));
    rec[10] = ay; rec[11] = az; rec[12] = wxv; rec[13] = wyv;

    __syncthreads();   // (6) image final

    float4* dst4 = reinterpret_cast<float4*>(out_states) + (size_t)k * IMG_F4;
#pragma unroll
    for (int i = 0; i < 4; ++i) dst4[tid + 128 * i] = img4[tid + 128 * i];
    if (tid < 32) dst4[512 + tid] = img4[512 + tid];
}

extern "C" void kernel_launch(void* const* d_in, const int* in_sizes, int n_in,
                              void* d_out, int out_size)
{
    const float* state = (const float*)d_in[0];
    const float* pact  = (const float*)d_in[1];
    const float* Hmap  = (const float*)d_in[2];
    const float* Nrm   = (const float*)d_in[3];

    const int K = (in_sizes[1] / 2) / T_STEPS;
    float* out_states = (float*)d_out;
    float* out_pa     = (float*)d_out + (size_t)in_sizes[0];

    car_dyn_kernel<<<K, 128>>>(state, pact, Hmap, Nrm, out_states, out_pa);
}

// round 5
// speedup vs baseline: 1.2773x; 1.1202x over previous
#include <cuda_runtime.h>
#include <cstdint>

#define FULLM 0xffffffffu

namespace {
constexpr int T_STEPS = 128;
constexpr int NCH = 17;
constexpr int IMG_FLOATS = T_STEPS * NCH;   // 2176
constexpr int IMG_F4 = IMG_FLOATS / 4;      // 544
}

// ---- JAX Brent-Kung 128-scan, decomposed: per-warp upsweep, 4-wide top
// tree through smem totals, per-warp downsweep with prefix injection.
// Bit-identical to the flat jnp.cumsum association (verified R4). ----

__device__ __forceinline__ float scan_up1(float r, int lane) {
#pragma unroll
    for (int h = 1; h <= 16; h <<= 1) {
        float u = __shfl_up_sync(FULLM, r, h);
        if ((lane & (2 * h - 1)) == (2 * h - 1)) r = __fadd_rn(u, r);
    }
    return r;
}

__device__ __forceinline__ void scan_up2(float& a, float& b, int lane) {
#pragma unroll
    for (int h = 1; h <= 16; h <<= 1) {
        float ua = __shfl_up_sync(FULLM, a, h);
        float ub = __shfl_up_sync(FULLM, b, h);
        if ((lane & (2 * h - 1)) == (2 * h - 1)) {
            a = __fadd_rn(ua, a);
            b = __fadd_rn(ub, b);
        }
    }
}

__device__ __forceinline__ float scan_down1(float r, int lane, int w,
                                            const float* __restrict__ T) {
    const float s1 = __fadd_rn(T[0], T[1]);
    const float S2 = __fadd_rn(s1, T[2]);
    const float S3 = __fadd_rn(s1, __fadd_rn(T[2], T[3]));
    const float E  = (w == 1) ? T[0] : (w == 2) ? s1 : S2;
    const float Sw = (w == 0) ? T[0] : (w == 1) ? s1 : (w == 2) ? S2 : S3;
    if (lane == 31) r = Sw;
#pragma unroll
    for (int h = 16; h >= 1; h >>= 1) {
        float u = __shfl_up_sync(FULLM, r, h);
        if (lane == h - 1) u = E;
        const bool act = ((lane & (2 * h - 1)) == (h - 1)) &&
                         (w > 0 || lane >= 2 * h);
        if (act) r = __fadd_rn(u, r);
    }
    return r;
}

__device__ __forceinline__ void scan_down2(float& a, float& b, int lane, int w,
                                           const float* __restrict__ Ta,
                                           const float* __restrict__ Tb) {
    const float s1a = __fadd_rn(Ta[0], Ta[1]);
    const float S2a = __fadd_rn(s1a, Ta[2]);
    const float S3a = __fadd_rn(s1a, __fadd_rn(Ta[2], Ta[3]));
    const float Ea  = (w == 1) ? Ta[0] : (w == 2) ? s1a : S2a;
    const float Swa = (w == 0) ? Ta[0] : (w == 1) ? s1a : (w == 2) ? S2a : S3a;
    const float s1b = __fadd_rn(Tb[0], Tb[1]);
    const float S2b = __fadd_rn(s1b, Tb[2]);
    const float S3b = __fadd_rn(s1b, __fadd_rn(Tb[2], Tb[3]));
    const float Eb  = (w == 1) ? Tb[0] : (w == 2) ? s1b : S2b;
    const float Swb = (w == 0) ? Tb[0] : (w == 1) ? s1b : (w == 2) ? S2b : S3b;
    if (lane == 31) { a = Swa; b = Swb; }
#pragma unroll
    for (int h = 16; h >= 1; h >>= 1) {
        float ua = __shfl_up_sync(FULLM, a, h);
        float ub = __shfl_up_sync(FULLM, b, h);
        if (lane == h - 1) { ua = Ea; ub = Eb; }
        const bool act = ((lane & (2 * h - 1)) == (h - 1)) &&
                         (w > 0 || lane >= 2 * h);
        if (act) { a = __fadd_rn(ua, a); b = __fadd_rn(ub, b); }
    }
}

__device__ __forceinline__ void cp_async16(float4* dst_smem, const float4* src_gmem) {
    uint32_t s = (uint32_t)__cvta_generic_to_shared(dst_smem);
    asm volatile("cp.async.cg.shared.global [%0], [%1], 16;" ::
                 "r"(s), "l"(src_gmem));
}

__global__ __launch_bounds__(128, 12)
void car_dyn_kernel(const float* __restrict__ state,
                    const float* __restrict__ pact,
                    const float* __restrict__ Hmap,
                    const float* __restrict__ Nrm,
                    float* __restrict__ out_states,
                    float* __restrict__ out_pa)
{
    __shared__ __align__(16) float img[IMG_FLOATS];   // 8704 B working image
    __shared__ float tot[5][4];
    __shared__ float bnd[4][2];

    const int tid  = threadIdx.x;
    const int lane = tid & 31;
    const int w    = tid >> 5;
    const int k    = blockIdx.x;

    float4* img4 = reinterpret_cast<float4*>(img);
    const float4* src4 = reinterpret_cast<const float4*>(state) + (size_t)k * IMG_F4;
#pragma unroll
    for (int i = 0; i < 4; ++i) cp_async16(&img4[tid + 128 * i], &src4[tid + 128 * i]);
    if (tid < 32) cp_async16(&img4[512 + tid], &src4[512 + tid]);
    asm volatile("cp.async.commit_group;" ::: "memory");

    const float2 pa = reinterpret_cast<const float2*>(pact)[(size_t)k * T_STEPS + tid];

    // ---- scans 1&2: cumsum(pa * DT) (no smem dependence yet) ----
    float r0 = __fmul_rn(pa.x, 0.02f);
    float r1 = __fmul_rn(pa.y, 0.02f);
    scan_up2(r0, r1, lane);
    if (lane == 31) { tot[0][w] = r0; tot[1][w] = r1; }

    asm volatile("cp.async.wait_group 0;" ::: "memory");
    __syncthreads();   // (1) image + warp totals ready

    scan_down2(r0, r1, lane, w, tot[0], tot[1]);

    float* rec = img + tid * NCH;   // base 17*tid -> conflict-free scalars

    // ---- controls ----
    const float s15 = rec[15], s16 = rec[16];
    float c0 = fminf(fmaxf(__fadd_rn(s15, __fmul_rn(4.0f, r0)), -1.f), 1.f);
    float c1 = fminf(fmaxf(__fadd_rn(s16, __fmul_rn(4.0f, r1)), -1.f), 1.f);
    c1 = fminf(fmaxf(c1, 0.f), 0.5f);
    const float cm0 = __fsub_rn(c0, s15);
    const float cm1 = __fsub_rn(c1, s16);
    rec[15] = c0; rec[16] = c1;
    rec[7] = 0.f; rec[8] = 0.f;      // vy, vz (ch9 = ax passes through)

    // ---- dynamics elementwise ----
    const float Kc = __fdiv_rn(tanf(c0), 0.5f);
    const float vx = __fmul_rn(c1, 17.0f);
    const float dS = __fmul_rn(vx, 0.02f);
    const float w1 = __fmul_rn(vx, Kc);
    const float a0 = fminf(fmaxf(__fmul_rn(vx, w1), -14.f), 14.f);
    const float wz = __fdiv_rn(a0, fminf(fmaxf(vx, 1.f), 25.f));
    rec[6] = vx; rec[14] = wz;

    // ---- scan 3 upsweep (wz) + cm boundary exchange, one sync ----
    float r2 = scan_up1(wz, lane);
    if (lane == 31) { tot[2][w] = r2; bnd[w][0] = cm0; bnd[w][1] = cm1; }
    __syncthreads();   // (2)

    // ---- new_pa straight to global ----
    {
        float pm0 = __shfl_up_sync(FULLM, cm0, 1);
        float pm1 = __shfl_up_sync(FULLM, cm1, 1);
        if (lane == 0 && w > 0) { pm0 = bnd[w - 1][0]; pm1 = bnd[w - 1][1]; }
        float np0 = __fdiv_rn(__fsub_rn(cm0, pm0), 0.08f);
        float np1 = __fdiv_rn(__fsub_rn(cm1, pm1), 0.08f);
        if (tid == 0) { np0 = pa.x; np1 = pa.y; }
        reinterpret_cast<float2*>(out_pa)[(size_t)k * T_STEPS + tid] =
            make_float2(np0, np1);
    }

    r2 = scan_down1(r2, lane, w, tot[2]);
    const float yaw = __fadd_rn(rec[5], __fmul_rn(0.02f, r2));
    rec[5] = yaw;
    const float cy = cosf(yaw);
    const float sy = sinf(yaw);

    // ---- scans 4&5: x, y ----
    float r3 = __fmul_rn(dS, cy);
    float r4 = __fmul_rn(dS, sy);
    scan_up2(r3, r4, lane);
    if (lane == 31) { tot[3][w] = r3; tot[4][w] = r4; }
    __syncthreads();   // (3)
    scan_down2(r3, r4, lane, w, tot[3], tot[4]);
    const float x = __fadd_rn(rec[0], r3);
    const float y = __fadd_rn(rec[1], r4);
    rec[0] = x; rec[1] = y;

    // ---- BEV gather ----
    int iX = (int)(__fmul_rn(__fadd_rn(x, 32.f), 4.f));
    int iY = (int)(__fmul_rn(__fadd_rn(y, 32.f), 4.f));
    iX = min(max(iX, 0), 255);
    iY = min(max(iY, 0), 255);
    const int g = iY * 256 + iX;
    const float z  = __ldg(Hmap + g);
    const float nx = __ldg(Nrm + 3 * g + 0);
    const float ny = __ldg(Nrm + 3 * g + 1);
    const float nz = __ldg(Nrm + 3 * g + 2);

    const float lz = __fsub_rn(__fmul_rn(nx, sy), __fmul_rn(ny, cy));
    const float lx = __fsub_rn(0.f, __fmul_rn(nz, sy));
    const float ly = __fmul_rn(nz, cy);
    const float roll = asinf(lz);
    const float fz = __fsub_rn(__fmul_rn(lx, ny), __fmul_rn(ly, nx));
    const float pitch = -asinf(fz);
    rec[2] = z; rec[3] = roll; rec[4] = pitch;

    // ---- roll/pitch boundary exchange + diffs ----
    if (lane == 31) { bnd[w][0] = roll; bnd[w][1] = pitch; }
    __syncthreads();   // (4)
    float pr = __shfl_up_sync(FULLM, roll, 1);
    float pp = __shfl_up_sync(FULLM, pitch, 1);
    if (lane == 0 && w > 0) { pr = bnd[w - 1][0]; pp = bnd[w - 1][1]; }
    float wxv = __fdiv_rn(__fsub_rn(roll, pr), 0.02f);
    float wyv = __fdiv_rn(__fsub_rn(pitch, pp), 0.02f);
    if (tid == 0) { wxv = rec[12]; wyv = rec[13]; }   // input ch12/13 intact
    // sin(asin(lz)) == lz to ~1 ulp; ay is not amplified downstream
    const float ay = __fadd_rn(__fmul_rn(vx, wz), __fmul_rn(9.8f, lz));
    const float az = __fadd_rn(__fmul_rn(__fsub_rn(0.f, vx), wyv),
                               __fmul_rn(9.8f, nz));
    rec[10] = ay; rec[11] = az; rec[12] = wxv; rec[13] = wyv;

    __syncthreads();   // (5) image final

    float4* dst4 = reinterpret_cast<float4*>(out_states) + (size_t)k * IMG_F4;
#pragma unroll
    for (int i = 0; i < 4; ++i) dst4[tid + 128 * i] = img4[tid + 128 * i];
    if (tid < 32) dst4[512 + tid] = img4[512 + tid];
}

extern "C" void kernel_launch(void* const* d_in, const int* in_sizes, int n_in,
                              void* d_out, int out_size)
{
    const float* state = (const float*)d_in[0];
    const float* pact  = (const float*)d_in[1];
    const float* Hmap  = (const float*)d_in[2];
    const float* Nrm   = (const float*)d_in[3];

    const int K = (in_sizes[1] / 2) / T_STEPS;
    float* out_states = (float*)d_out;
    float* out_pa     = (float*)d_out + (size_t)in_sizes[0];

    car_dyn_kernel<<<K, 128>>>(state, pact, Hmap, Nrm, out_states, out_pa);
}

// round 7
// speedup vs baseline: 1.4265x; 1.1168x over previous
#include <cuda_runtime.h>
#include <cstdint>

#define FULLM 0xffffffffu

namespace {
constexpr int T_STEPS = 128;
constexpr int NCH = 17;
constexpr int IMG_FLOATS = T_STEPS * NCH;       // 2176
constexpr int IMG_F4 = IMG_FLOATS / 4;          // 544
constexpr int IMG_BYTES = IMG_FLOATS * 4;       // 8704
}

// ---- JAX Brent-Kung 128-scan, decomposed: per-warp upsweep, 4-wide top
// tree through smem totals, per-warp downsweep with prefix injection.
// Bit-identical to the flat jnp.cumsum association (verified R4/R5). ----

__device__ __forceinline__ float scan_up1(float r, int lane) {
#pragma unroll
    for (int h = 1; h <= 16; h <<= 1) {
        float u = __shfl_up_sync(FULLM, r, h);
        if ((lane & (2 * h - 1)) == (2 * h - 1)) r = __fadd_rn(u, r);
    }
    return r;
}

__device__ __forceinline__ void scan_up2(float& a, float& b, int lane) {
#pragma unroll
    for (int h = 1; h <= 16; h <<= 1) {
        float ua = __shfl_up_sync(FULLM, a, h);
        float ub = __shfl_up_sync(FULLM, b, h);
        if ((lane & (2 * h - 1)) == (2 * h - 1)) {
            a = __fadd_rn(ua, a);
            b = __fadd_rn(ub, b);
        }
    }
}

__device__ __forceinline__ float scan_down1(float r, int lane, int w,
                                            const float* __restrict__ T) {
    const float s1 = __fadd_rn(T[0], T[1]);
    const float S2 = __fadd_rn(s1, T[2]);
    const float S3 = __fadd_rn(s1, __fadd_rn(T[2], T[3]));
    const float E  = (w == 1) ? T[0] : (w == 2) ? s1 : S2;
    const float Sw = (w == 0) ? T[0] : (w == 1) ? s1 : (w == 2) ? S2 : S3;
    if (lane == 31) r = Sw;
#pragma unroll
    for (int h = 16; h >= 1; h >>= 1) {
        float u = __shfl_up_sync(FULLM, r, h);
        if (lane == h - 1) u = E;
        const bool act = ((lane & (2 * h - 1)) == (h - 1)) &&
                         (w > 0 || lane >= 2 * h);
        if (act) r = __fadd_rn(u, r);
    }
    return r;
}

__device__ __forceinline__ void scan_down2(float& a, float& b, int lane, int w,
                                           const float* __restrict__ Ta,
                                           const float* __restrict__ Tb) {
    const float s1a = __fadd_rn(Ta[0], Ta[1]);
    const float S2a = __fadd_rn(s1a, Ta[2]);
    const float S3a = __fadd_rn(s1a, __fadd_rn(Ta[2], Ta[3]));
    const float Ea  = (w == 1) ? Ta[0] : (w == 2) ? s1a : S2a;
    const float Swa = (w == 0) ? Ta[0] : (w == 1) ? s1a : (w == 2) ? S2a : S3a;
    const float s1b = __fadd_rn(Tb[0], Tb[1]);
    const float S2b = __fadd_rn(s1b, Tb[2]);
    const float S3b = __fadd_rn(s1b, __fadd_rn(Tb[2], Tb[3]));
    const float Eb  = (w == 1) ? Tb[0] : (w == 2) ? s1b : S2b;
    const float Swb = (w == 0) ? Tb[0] : (w == 1) ? s1b : (w == 2) ? S2b : S3b;
    if (lane == 31) { a = Swa; b = Swb; }
#pragma unroll
    for (int h = 16; h >= 1; h >>= 1) {
        float ua = __shfl_up_sync(FULLM, a, h);
        float ub = __shfl_up_sync(FULLM, b, h);
        if (lane == h - 1) { ua = Ea; ub = Eb; }
        const bool act = ((lane & (2 * h - 1)) == (h - 1)) &&
                         (w > 0 || lane >= 2 * h);
        if (act) { a = __fadd_rn(ua, a); b = __fadd_rn(ub, b); }
    }
}

__device__ __forceinline__ void cp_async16(float4* dst_smem, const float4* src_gmem) {
    uint32_t s = (uint32_t)__cvta_generic_to_shared(dst_smem);
    asm volatile("cp.async.cg.shared.global [%0], [%1], 16;" ::
                 "r"(s), "l"(src_gmem));
}

__global__ __launch_bounds__(128, 14)
void car_dyn_kernel(const float* __restrict__ state,
                    const float* __restrict__ pact,
                    const float* __restrict__ Hmap,
                    const float* __restrict__ Nrm,
                    float* __restrict__ out_states,
                    float* __restrict__ out_pa)
{
    __shared__ __align__(16) float img[IMG_FLOATS];   // 8704 B working image
    __shared__ float tot[5][4];
    __shared__ float bnd[4][2];

    const int tid  = threadIdx.x;
    const int lane = tid & 31;
    const int w    = tid >> 5;
    const int k    = blockIdx.x;

    float4* img4 = reinterpret_cast<float4*>(img);
    const float4* src4 = reinterpret_cast<const float4*>(state) + (size_t)k * IMG_F4;
#pragma unroll
    for (int i = 0; i < 4; ++i) cp_async16(&img4[tid + 128 * i], &src4[tid + 128 * i]);
    if (tid < 32) cp_async16(&img4[512 + tid], &src4[512 + tid]);
    asm volatile("cp.async.commit_group;" ::: "memory");

    const float2 pa = reinterpret_cast<const float2*>(pact)[(size_t)k * T_STEPS + tid];

    // ---- scans 1&2: cumsum(pa * DT) (overlap with in-copy) ----
    float r0 = __fmul_rn(pa.x, 0.02f);
    float r1 = __fmul_rn(pa.y, 0.02f);
    scan_up2(r0, r1, lane);
    if (lane == 31) { tot[0][w] = r0; tot[1][w] = r1; }

    asm volatile("cp.async.wait_group 0;" ::: "memory");
    __syncthreads();   // (1) image + warp totals ready

    scan_down2(r0, r1, lane, w, tot[0], tot[1]);

    float* rec = img + tid * NCH;   // base 17*tid -> conflict-free scalars

    // ---- controls ----
    const float s15 = rec[15], s16 = rec[16];
    float c0 = fminf(fmaxf(__fadd_rn(s15, __fmul_rn(4.0f, r0)), -1.f), 1.f);
    float c1 = fminf(fmaxf(__fadd_rn(s16, __fmul_rn(4.0f, r1)), -1.f), 1.f);
    c1 = fminf(fmaxf(c1, 0.f), 0.5f);
    const float cm0 = __fsub_rn(c0, s15);
    const float cm1 = __fsub_rn(c1, s16);
    rec[15] = c0; rec[16] = c1;
    rec[7] = 0.f; rec[8] = 0.f;      // vy, vz (ch9 = ax passes through)

    // ---- dynamics elementwise ----
    const float Kc = __fdiv_rn(tanf(c0), 0.5f);
    const float vx = __fmul_rn(c1, 17.0f);
    const float dS = __fmul_rn(vx, 0.02f);
    const float w1 = __fmul_rn(vx, Kc);
    const float a0 = fminf(fmaxf(__fmul_rn(vx, w1), -14.f), 14.f);
    const float wz = __fdiv_rn(a0, fminf(fmaxf(vx, 1.f), 25.f));
    rec[6] = vx; rec[14] = wz;

    // ---- scan 3 upsweep (wz) + cm boundary exchange, one sync ----
    float r2 = scan_up1(wz, lane);
    if (lane == 31) { tot[2][w] = r2; bnd[w][0] = cm0; bnd[w][1] = cm1; }
    __syncthreads();   // (2)

    // ---- new_pa straight to global ----
    {
        float pm0 = __shfl_up_sync(FULLM, cm0, 1);
        float pm1 = __shfl_up_sync(FULLM, cm1, 1);
        if (lane == 0 && w > 0) { pm0 = bnd[w - 1][0]; pm1 = bnd[w - 1][1]; }
        float np0 = __fdiv_rn(__fsub_rn(cm0, pm0), 0.08f);
        float np1 = __fdiv_rn(__fsub_rn(cm1, pm1), 0.08f);
        if (tid == 0) { np0 = pa.x; np1 = pa.y; }
        reinterpret_cast<float2*>(out_pa)[(size_t)k * T_STEPS + tid] =
            make_float2(np0, np1);
    }

    r2 = scan_down1(r2, lane, w, tot[2]);
    const float yaw = __fadd_rn(rec[5], __fmul_rn(0.02f, r2));
    rec[5] = yaw;
    const float cy = cosf(yaw);
    const float sy = sinf(yaw);

    // ---- scans 4&5: x, y ----
    float r3 = __fmul_rn(dS, cy);
    float r4 = __fmul_rn(dS, sy);
    scan_up2(r3, r4, lane);
    if (lane == 31) { tot[3][w] = r3; tot[4][w] = r4; }
    __syncthreads();   // (3)
    scan_down2(r3, r4, lane, w, tot[3], tot[4]);
    const float x = __fadd_rn(rec[0], r3);
    const float y = __fadd_rn(rec[1], r4);
    rec[0] = x; rec[1] = y;

    // ---- BEV gather ----
    int iX = (int)(__fmul_rn(__fadd_rn(x, 32.f), 4.f));
    int iY = (int)(__fmul_rn(__fadd_rn(y, 32.f), 4.f));
    iX = min(max(iX, 0), 255);
    iY = min(max(iY, 0), 255);
    const int g = iY * 256 + iX;
    const float z  = __ldg(Hmap + g);
    const float nx = __ldg(Nrm + 3 * g + 0);
    const float ny = __ldg(Nrm + 3 * g + 1);
    const float nz = __ldg(Nrm + 3 * g + 2);

    const float lz = __fsub_rn(__fmul_rn(nx, sy), __fmul_rn(ny, cy));
    const float lx = __fsub_rn(0.f, __fmul_rn(nz, sy));
    const float ly = __fmul_rn(nz, cy);
    const float roll = asinf(lz);
    const float fz = __fsub_rn(__fmul_rn(lx, ny), __fmul_rn(ly, nx));
    const float pitch = -asinf(fz);
    rec[2] = z; rec[3] = roll; rec[4] = pitch;

    // ---- roll/pitch boundary exchange + diffs ----
    if (lane == 31) { bnd[w][0] = roll; bnd[w][1] = pitch; }
    __syncthreads();   // (4)
    float pr = __shfl_up_sync(FULLM, roll, 1);
    float pp = __shfl_up_sync(FULLM, pitch, 1);
    if (lane == 0 && w > 0) { pr = bnd[w - 1][0]; pp = bnd[w - 1][1]; }
    float wxv = __fdiv_rn(__fsub_rn(roll, pr), 0.02f);
    float wyv = __fdiv_rn(__fsub_rn(pitch, pp), 0.02f);
    if (tid == 0) { wxv = rec[12]; wyv = rec[13]; }   // input ch12/13 intact
    const float ay = __fadd_rn(__fmul_rn(vx, wz), __fmul_rn(9.8f, lz));
    const float az = __fadd_rn(__fmul_rn(__fsub_rn(0.f, vx), wyv),
                               __fmul_rn(9.8f, nz));
    rec[10] = ay; rec[11] = az; rec[12] = wxv; rec[13] = wyv;

    __syncthreads();   // (5) image final

    // ---- single bulk DMA: smem -> global (example-verified form) ----
    if (tid == 0) {
        float* dst = out_states + (size_t)k * IMG_FLOATS;
        const uint32_t img_s = (uint32_t)__cvta_generic_to_shared(img);
        asm volatile("fence.proxy.async.shared::cta;" ::: "memory");
        asm volatile(
            "cp.async.bulk.global.shared::cta.bulk_group [%0], [%1], %2;"
            :: "l"(dst), "r"(img_s), "r"((uint32_t)IMG_BYTES) : "memory");
        asm volatile("cp.async.bulk.commit_group;" ::: "memory");
        asm volatile("cp.async.bulk.wait_group.read 0;" ::: "memory");
    }
}

extern "C" void kernel_launch(void* const* d_in, const int* in_sizes, int n_in,
                              void* d_out, int out_size)
{
    const float* state = (const float*)d_in[0];
    const float* pact  = (const float*)d_in[1];
    const float* Hmap  = (const float*)d_in[2];
    const float* Nrm   = (const float*)d_in[3];

    const int K = (in_sizes[1] / 2) / T_STEPS;
    float* out_states = (float*)d_out;
    float* out_pa     = (float*)d_out + (size_t)in_sizes[0];

    car_dyn_kernel<<<K, 128>>>(state, pact, Hmap, Nrm, out_states, out_pa);
}